// round 3
// baseline (speedup 1.0000x reference)
#include <cuda_runtime.h>
#include <stdint.h>

#define NN      100001
#define EE      6400000
#define NSTEPS  100

// Static device scratch (allocation-free per harness rules).
__device__ int   g_di[EE];
__device__ int   g_dj[EE];
__device__ float g_w [EE];
__device__ float g_sa[NN];
__device__ float g_sb[NN];
__device__ int   g_maxbits;
__device__ int   g_is64;

// Detect whether adj_ind arrived as int64 or int32 (JAX x64-disabled silently
// demotes jnp.int64 -> int32). Reads only the first 512 bytes — safe for both
// layouts. int32 data viewed as int64 = lo + hi*2^32 >= 2^32 (out of range)
// unless hi==0, so "all 64 in range" reliably identifies a true int64 layout.
__global__ void detect_kernel(const void* __restrict__ adj) {
    const long long* a64 = (const long long*)adj;
    int ok = 1;
    for (int i = 0; i < 64; ++i) {
        long long v = a64[i];
        if (v < 0 || v >= NN) { ok = 0; break; }
    }
    g_is64 = ok;
}

// Pack indices -> int32, pre-apply DT and the row-0 masking rules:
//   di==0 && dj==0 -> weight 1.0 ; di==0 && dj!=0 -> weight 0.0 ; else 0.1*val
// Out-of-range indices (defensive) -> weight 0, index 0.
__device__ __forceinline__ void store_edge(int e, int di, int dj, float v) {
    float w = (di == 0) ? ((dj == 0) ? 1.0f : 0.0f) : 0.1f * v;
    if ((unsigned)di >= NN) { di = 0; w = 0.0f; }
    if ((unsigned)dj >= NN) { dj = 0; w = 0.0f; }
    g_di[e] = di;
    g_dj[e] = dj;
    g_w[e]  = w;
}

__global__ void prep64_kernel(const long long* __restrict__ adj,
                              const float* __restrict__ val, int E) {
    if (!g_is64) return;
    int stride = gridDim.x * blockDim.x;
    for (int e = blockIdx.x * blockDim.x + threadIdx.x; e < E; e += stride)
        store_edge(e, (int)adj[e], (int)adj[(long long)E + e], val[e]);
}

__global__ void prep32_kernel(const int* __restrict__ adj,
                              const float* __restrict__ val, int E) {
    if (g_is64) return;
    int stride = gridDim.x * blockDim.x;
    for (int e = blockIdx.x * blockDim.x + threadIdx.x; e < E; e += stride)
        store_edge(e, adj[e], adj[E + e], val[e]);
}

__global__ void init_kernel() {
    int i = blockIdx.x * blockDim.x + threadIdx.x;
    if (i < NN) g_sa[i] = 1.0f;
    if (i == 0) g_maxbits = 0;
}

// out = diag part of M * in; doubles as the zero-init before edge atomics.
// Row 0: out[0] = in[0] (the (0,0)=1 entry replaces the diagonal there).
__global__ void diag_kernel(const float* __restrict__ in, float* __restrict__ out) {
    int i = blockIdx.x * blockDim.x + threadIdx.x;
    if (i < NN) out[i] = (i == 0) ? in[0] : 0.9f * in[i];
}

// Scatter-add all edge contributions: out[di] += w * in[dj]
__global__ void edge_kernel(const float* __restrict__ in, float* __restrict__ out,
                            int E4, int E) {
    int tid = blockIdx.x * blockDim.x + threadIdx.x;
    int stride = gridDim.x * blockDim.x;
    const int4*   di4 = reinterpret_cast<const int4*>(g_di);
    const int4*   dj4 = reinterpret_cast<const int4*>(g_dj);
    const float4* w4  = reinterpret_cast<const float4*>(g_w);
    for (int g = tid; g < E4; g += stride) {
        int4   a = di4[g];
        int4   b = dj4[g];
        float4 w = w4[g];
        float m0 = w.x * __ldg(in + b.x);
        float m1 = w.y * __ldg(in + b.y);
        float m2 = w.z * __ldg(in + b.z);
        float m3 = w.w * __ldg(in + b.w);
        atomicAdd(out + a.x, m0);
        atomicAdd(out + a.y, m1);
        atomicAdd(out + a.z, m2);
        atomicAdd(out + a.w, m3);
    }
    int tail = E - E4 * 4;
    if (tid < tail) {
        int e = E4 * 4 + tid;
        atomicAdd(out + g_di[e], g_w[e] * __ldg(in + g_dj[e]));
    }
}

__global__ void maxred_kernel(const float* __restrict__ s) {
    __shared__ float sm[8];
    float m = 0.0f;
    int stride = gridDim.x * blockDim.x;
    for (int i = blockIdx.x * blockDim.x + threadIdx.x + 1; i < NN; i += stride)
        m = fmaxf(m, fabsf(s[i]));
    #pragma unroll
    for (int o = 16; o; o >>= 1) m = fmaxf(m, __shfl_xor_sync(0xffffffffu, m, o));
    if ((threadIdx.x & 31) == 0) sm[threadIdx.x >> 5] = m;
    __syncthreads();
    if (threadIdx.x < 32) {
        m = (threadIdx.x < (blockDim.x >> 5)) ? sm[threadIdx.x] : 0.0f;
        #pragma unroll
        for (int o = 16; o; o >>= 1) m = fmaxf(m, __shfl_xor_sync(0xffffffffu, m, o));
        // all values >= 0 -> integer-bit compare is order-preserving
        if (threadIdx.x == 0) atomicMax(&g_maxbits, __float_as_int(m));
    }
}

__global__ void norm_kernel(const float* __restrict__ s, float* __restrict__ out) {
    int i = blockIdx.x * blockDim.x + threadIdx.x;
    if (i < NN) {
        float mv = __int_as_float(g_maxbits);
        out[i] = (i == 0) ? 1.0f : s[i] / mv;
    }
}

extern "C" void kernel_launch(void* const* d_in, const int* in_sizes, int n_in,
                              void* d_out, int out_size) {
    const void*  adj = d_in[0];
    const float* val = (const float*)d_in[1];
    int E = in_sizes[1];
    if (E > EE) E = EE;
    int E4 = E / 4;

    float *sa = nullptr, *sb = nullptr;
    cudaGetSymbolAddress((void**)&sa, g_sa);
    cudaGetSymbolAddress((void**)&sb, g_sb);

    detect_kernel<<<1, 1>>>(adj);
    prep64_kernel<<<2048, 256>>>((const long long*)adj, val, E);
    prep32_kernel<<<2048, 256>>>((const int*)adj, val, E);
    init_kernel<<<(NN + 255) / 256, 256>>>();

    float* cur = sa;
    float* nxt = sb;
    for (int t = 0; t < NSTEPS; ++t) {
        diag_kernel<<<(NN + 255) / 256, 256>>>(cur, nxt);
        edge_kernel<<<2048, 256>>>(cur, nxt, E4, E);
        float* tmp = cur; cur = nxt; nxt = tmp;
    }

    maxred_kernel<<<512, 256>>>(cur);
    norm_kernel<<<(NN + 255) / 256, 256>>>(cur, (float*)d_out);
}